// round 5
// baseline (speedup 1.0000x reference)
#include <cuda_runtime.h>
#include <cuda_bf16.h>
#include <math.h>

#define N_NODES 50000
#define N_EDGES 800000
#define HID 256
#define HEADS 4
#define DH 64
#define NEG 0.2f

// ------------------------- device scratch -------------------------
__device__ float g_feat[N_NODES * HID];          // projected features (per layer)
__device__ float g_hA[N_NODES * HID];            // layer-0 output
__device__ float g_hB[N_NODES * HID];            // layer-1 output
__device__ float g_el[N_NODES * HEADS];
__device__ float g_er[N_NODES * HEADS];
__device__ float g_e[(size_t)HEADS * N_EDGES];   // per-head edge scores (CSR slot order)
__device__ int   g_deg[N_NODES];
__device__ int   g_pos[N_NODES];
__device__ int   g_off[N_NODES + 1];
__device__ int   g_srcs[N_EDGES];                // src node per CSR slot

// ------------------------- CSR build -------------------------
__global__ void zero_kernel() {
    int i = blockIdx.x * blockDim.x + threadIdx.x;
    if (i < N_NODES) { g_deg[i] = 0; g_pos[i] = 0; }
}

__global__ void hist_kernel(const int* __restrict__ dst) {
    int i = blockIdx.x * blockDim.x + threadIdx.x;
    if (i < N_EDGES) atomicAdd(&g_deg[dst[i]], 1);
}

// single-block exclusive scan of g_deg -> g_off (1024 threads, segmented)
__global__ void scan_offsets_kernel() {
    __shared__ int sums[1024];
    const int SEG = (N_NODES + 1023) / 1024;   // 49
    int t = threadIdx.x;
    int b0 = t * SEG;
    int s = 0;
    for (int i = 0; i < SEG; i++) {
        int idx = b0 + i;
        if (idx < N_NODES) s += g_deg[idx];
    }
    sums[t] = s;
    __syncthreads();
    for (int o = 1; o < 1024; o <<= 1) {
        int v = (t >= o) ? sums[t - o] : 0;
        __syncthreads();
        sums[t] += v;
        __syncthreads();
    }
    int run = sums[t] - s;   // exclusive base of this segment
    for (int i = 0; i < SEG; i++) {
        int idx = b0 + i;
        if (idx < N_NODES) { g_off[idx] = run; run += g_deg[idx]; }
    }
    if (t == 1023) g_off[N_NODES] = sums[1023];
}

__global__ void scatter_kernel(const int* __restrict__ src, const int* __restrict__ dst) {
    int i = blockIdx.x * blockDim.x + threadIdx.x;
    if (i < N_EDGES) {
        int d = dst[i];
        int p = atomicAdd(&g_pos[d], 1);
        g_srcs[g_off[d] + p] = src[i];
    }
}

// ------------------------- TF32 tensor-core GEMM -------------------------
// C[M,256] = A[M,K] @ B[K,256]. Block tile 128x128, BK=32, 8 warps (2x4),
// warp tile 64x32 = 4x4 tiles of m16n8k8. XOR-swizzled smem, ping-pong bufs.
#define BM 128
#define BN 128
#define BK 32

__device__ __forceinline__ unsigned f2tf32(float f) {
    unsigned u;
    asm("cvt.rna.tf32.f32 %0, %1;" : "=r"(u) : "f"(f));
    return u;
}

__device__ __forceinline__ void mma_tf32(float* c, const unsigned* a, const unsigned* b) {
    asm volatile(
        "mma.sync.aligned.m16n8k8.row.col.f32.tf32.tf32.f32 "
        "{%0,%1,%2,%3}, {%4,%5,%6,%7}, {%8,%9}, {%0,%1,%2,%3};\n"
        : "+f"(c[0]), "+f"(c[1]), "+f"(c[2]), "+f"(c[3])
        : "r"(a[0]), "r"(a[1]), "r"(a[2]), "r"(a[3]), "r"(b[0]), "r"(b[1]));
}

extern __shared__ unsigned g_smem[];   // [2][BM*BK] A  +  [2][BK*BN] B

__global__ __launch_bounds__(256) void gemm_tc_kernel(
    const float* __restrict__ A, const float* __restrict__ B, float* __restrict__ C,
    int M, int K)
{
    unsigned* As = g_smem;                 // 2 * BM*BK
    unsigned* Bs = g_smem + 2 * BM * BK;   // 2 * BK*BN

    int tid = threadIdx.x;
    int lane = tid & 31;
    int w = tid >> 5;
    int wm = w >> 2;          // 0..1  (64 rows each)
    int wn = w & 3;           // 0..3  (32 cols each)
    int rowBase = blockIdx.y * BM;
    int colBase = blockIdx.x * BN;

    float c[4][4][4];
#pragma unroll
    for (int t = 0; t < 4; t++)
#pragma unroll
        for (int u = 0; u < 4; u++)
#pragma unroll
            for (int j = 0; j < 4; j++) c[t][u][j] = 0.f;

    // gmem load mapping (16 floats each side per thread)
    int am_ld = tid >> 3;            // 0..31 row within 32-row pass (4 passes)
    int ak_ld = (tid & 7) << 2;      // k4: 0..28
    int bk_ld = tid >> 5;            // 0..7  k within 8-row pass (4 passes)
    int bn_ld = (tid & 31) << 2;     // 0..124

    float4 ra[4];
    float4 rb[4];

#define LOAD_TILE(k0)                                                          \
    {                                                                          \
        _Pragma("unroll")                                                      \
        for (int p = 0; p < 4; p++) {                                          \
            int row = rowBase + p * 32 + am_ld;                                \
            ra[p] = (row < M)                                                  \
                ? *(const float4*)(A + (size_t)row * K + (k0) + ak_ld)         \
                : make_float4(0.f, 0.f, 0.f, 0.f);                             \
        }                                                                      \
        _Pragma("unroll")                                                      \
        for (int p = 0; p < 4; p++) {                                          \
            int kk = (k0) + p * 8 + bk_ld;                                     \
            rb[p] = *(const float4*)(B + (size_t)kk * 256 + colBase + bn_ld);  \
        }                                                                      \
    }

#define STORE_TILE(buf)                                                        \
    {                                                                          \
        unsigned* Ab = As + (buf) * (BM * BK);                                 \
        unsigned* Bb = Bs + (buf) * (BK * BN);                                 \
        _Pragma("unroll")                                                      \
        for (int p = 0; p < 4; p++) {                                          \
            int m = p * 32 + am_ld;                                            \
            int idx = m * BK + (ak_ld ^ ((m & 7) << 2));                       \
            uint4 v;                                                           \
            v.x = f2tf32(ra[p].x); v.y = f2tf32(ra[p].y);                      \
            v.z = f2tf32(ra[p].z); v.w = f2tf32(ra[p].w);                      \
            *(uint4*)&Ab[idx] = v;                                             \
        }                                                                      \
        _Pragma("unroll")                                                      \
        for (int p = 0; p < 4; p++) {                                          \
            int k = p * 8 + bk_ld;                                             \
            int idx = k * BN + (bn_ld ^ ((k & 3) << 3));                       \
            uint4 v;                                                           \
            v.x = f2tf32(rb[p].x); v.y = f2tf32(rb[p].y);                      \
            v.z = f2tf32(rb[p].z); v.w = f2tf32(rb[p].w);                      \
            *(uint4*)&Bb[idx] = v;                                             \
        }                                                                      \
    }

    int KS = K / BK;
    LOAD_TILE(0);
    STORE_TILE(0);
    __syncthreads();

    for (int it = 0; it < KS; ++it) {
        int cur = it & 1;
        unsigned* Ab = As + cur * (BM * BK);
        unsigned* Bb = Bs + cur * (BK * BN);
        if (it + 1 < KS) LOAD_TILE((it + 1) * BK);

#pragma unroll
        for (int kk = 0; kk < 4; kk++) {
            int kb = kk * 8;
            unsigned af[4][4], bf[4][2];
#pragma unroll
            for (int t = 0; t < 4; t++) {
                int r  = wm * 64 + t * 16 + (lane >> 2);
                int r8 = r + 8;
                int c0 = kb + (lane & 3);
                int sw  = (r  & 7) << 2;
                int sw8 = (r8 & 7) << 2;
                af[t][0] = Ab[r  * BK + ( c0      ^ sw )];
                af[t][1] = Ab[r8 * BK + ( c0      ^ sw8)];
                af[t][2] = Ab[r  * BK + ((c0 + 4) ^ sw )];
                af[t][3] = Ab[r8 * BK + ((c0 + 4) ^ sw8)];
            }
#pragma unroll
            for (int u = 0; u < 4; u++) {
                int n  = wn * 32 + u * 8 + (lane >> 2);
                int k0 = kb + (lane & 3);
                int k1 = k0 + 4;
                bf[u][0] = Bb[k0 * BN + (n ^ ((k0 & 3) << 3))];
                bf[u][1] = Bb[k1 * BN + (n ^ ((k1 & 3) << 3))];
            }
#pragma unroll
            for (int t = 0; t < 4; t++)
#pragma unroll
                for (int u = 0; u < 4; u++)
                    mma_tf32(c[t][u], af[t], bf[u]);
        }

        if (it + 1 < KS) STORE_TILE((it + 1) & 1);
        __syncthreads();
    }

    // epilogue
#pragma unroll
    for (int t = 0; t < 4; t++) {
        int r  = rowBase + wm * 64 + t * 16 + (lane >> 2);
        int r8 = r + 8;
#pragma unroll
        for (int u = 0; u < 4; u++) {
            int col = colBase + wn * 32 + u * 8 + ((lane & 3) << 1);
            if (r  < M) *(float2*)(C + (size_t)r  * 256 + col) = make_float2(c[t][u][0], c[t][u][1]);
            if (r8 < M) *(float2*)(C + (size_t)r8 * 256 + col) = make_float2(c[t][u][2], c[t][u][3]);
        }
    }
#undef LOAD_TILE
#undef STORE_TILE
}

// ------------------------- el/er projections -------------------------
__global__ __launch_bounds__(256) void elr4_kernel(
    const float* __restrict__ al, const float* __restrict__ ar)
{
    int w = blockIdx.x * 8 + (threadIdx.x >> 5);
    if (w >= N_NODES * HEADS) return;
    int lane = threadIdx.x & 31;
    int n = w >> 2, h = w & 3;
    const float* f = g_feat + (size_t)n * HID + h * DH;
    float f0 = f[lane], f1 = f[lane + 32];
    float a0 = al[h * DH + lane], a1 = al[h * DH + lane + 32];
    float r0 = ar[h * DH + lane], r1 = ar[h * DH + lane + 32];
    float pe = f0 * a0 + f1 * a1;
    float pr = f0 * r0 + f1 * r1;
#pragma unroll
    for (int o = 16; o; o >>= 1) {
        pe += __shfl_xor_sync(0xffffffffu, pe, o);
        pr += __shfl_xor_sync(0xffffffffu, pr, o);
    }
    if (lane == 0) { g_el[w] = pe; g_er[w] = pr; }
}

__global__ __launch_bounds__(256) void elr1_kernel(
    const float* __restrict__ al, const float* __restrict__ ar)
{
    int n = blockIdx.x * 8 + (threadIdx.x >> 5);
    if (n >= N_NODES) return;
    int lane = threadIdx.x & 31;
    const float* f = g_feat + (size_t)n * HID;
    float pe = 0.f, pr = 0.f;
#pragma unroll
    for (int j = 0; j < 8; j++) {
        float fv = f[lane + 32 * j];
        pe += fv * al[lane + 32 * j];
        pr += fv * ar[lane + 32 * j];
    }
#pragma unroll
    for (int o = 16; o; o >>= 1) {
        pe += __shfl_xor_sync(0xffffffffu, pe, o);
        pr += __shfl_xor_sync(0xffffffffu, pr, o);
    }
    if (lane == 0) { g_el[n] = pe; g_er[n] = pr; }
}

// ------------------------- aggregation -------------------------
__global__ __launch_bounds__(256) void agg4_kernel(
    const float* __restrict__ bvec, float* __restrict__ out)
{
    int w = blockIdx.x * 8 + (threadIdx.x >> 5);
    if (w >= N_NODES * HEADS) return;
    int lane = threadIdx.x & 31;
    int n = w >> 2, h = w & 3;
    int beg = g_off[n], end = g_off[n + 1];
    float ern = g_er[w];
    float* eplane = g_e + (size_t)h * N_EDGES;

    float mx = -3.4e38f;
    for (int i = beg + lane; i < end; i += 32) {
        float ev = g_el[g_srcs[i] * HEADS + h] + ern;
        ev = (ev > 0.f) ? ev : ev * NEG;
        eplane[i] = ev;
        mx = fmaxf(mx, ev);
    }
#pragma unroll
    for (int o = 16; o; o >>= 1) mx = fmaxf(mx, __shfl_xor_sync(0xffffffffu, mx, o));

    float se = 0.f;
    for (int i = beg + lane; i < end; i += 32) {
        float ex = __expf(eplane[i] - mx);
        eplane[i] = ex;
        se += ex;
    }
#pragma unroll
    for (int o = 16; o; o >>= 1) se += __shfl_xor_sync(0xffffffffu, se, o);
    float inv = 1.f / se;
    __syncwarp();

    float acc0 = 0.f, acc1 = 0.f;
    for (int i = beg; i < end; i++) {
        float a = eplane[i] * inv;
        int s = g_srcs[i];
        const float* fr = g_feat + (size_t)s * HID + h * DH;
        acc0 = fmaf(a, fr[lane], acc0);
        acc1 = fmaf(a, fr[lane + 32], acc1);
    }
    float o0 = acc0 + bvec[h * DH + lane];
    float o1 = acc1 + bvec[h * DH + lane + 32];
    out[(size_t)n * HID + h * DH + lane]      = fmaxf(o0, 0.f);
    out[(size_t)n * HID + h * DH + lane + 32] = fmaxf(o1, 0.f);
}

__global__ __launch_bounds__(256) void agg1_kernel(
    const float* __restrict__ bvec, float* __restrict__ out)
{
    int n = blockIdx.x * 8 + (threadIdx.x >> 5);
    if (n >= N_NODES) return;
    int lane = threadIdx.x & 31;
    int beg = g_off[n], end = g_off[n + 1];
    float ern = g_er[n];

    float mx = -3.4e38f;
    for (int i = beg + lane; i < end; i += 32) {
        float ev = g_el[g_srcs[i]] + ern;
        ev = (ev > 0.f) ? ev : ev * NEG;
        g_e[i] = ev;
        mx = fmaxf(mx, ev);
    }
#pragma unroll
    for (int o = 16; o; o >>= 1) mx = fmaxf(mx, __shfl_xor_sync(0xffffffffu, mx, o));

    float se = 0.f;
    for (int i = beg + lane; i < end; i += 32) {
        float ex = __expf(g_e[i] - mx);
        g_e[i] = ex;
        se += ex;
    }
#pragma unroll
    for (int o = 16; o; o >>= 1) se += __shfl_xor_sync(0xffffffffu, se, o);
    float inv = 1.f / se;
    __syncwarp();

    float acc[8];
#pragma unroll
    for (int j = 0; j < 8; j++) acc[j] = 0.f;
    for (int i = beg; i < end; i++) {
        float a = g_e[i] * inv;
        int s = g_srcs[i];
        const float* fr = g_feat + (size_t)s * HID;
#pragma unroll
        for (int j = 0; j < 8; j++) acc[j] = fmaf(a, fr[lane + 32 * j], acc[j]);
    }
#pragma unroll
    for (int j = 0; j < 8; j++)
        out[(size_t)n * HID + lane + 32 * j] = acc[j] + bvec[lane + 32 * j];
}

// ------------------------- host launch -------------------------
extern "C" void kernel_launch(void* const* d_in, const int* in_sizes, int n_in,
                              void* d_out, int out_size)
{
    const float* feats = (const float*)d_in[0];
    const int*   src   = (const int*)d_in[1];
    const int*   dst   = (const int*)d_in[2];
    const float* W0  = (const float*)d_in[3];
    const float* al0 = (const float*)d_in[4];
    const float* ar0 = (const float*)d_in[5];
    const float* b0  = (const float*)d_in[6];
    const float* W1  = (const float*)d_in[7];
    const float* al1 = (const float*)d_in[8];
    const float* ar1 = (const float*)d_in[9];
    const float* b1  = (const float*)d_in[10];
    const float* W2  = (const float*)d_in[11];
    const float* al2 = (const float*)d_in[12];
    const float* ar2 = (const float*)d_in[13];
    const float* b2  = (const float*)d_in[14];
    float* out = (float*)d_out;

    float *p_feat, *p_hA, *p_hB;
    cudaGetSymbolAddress((void**)&p_feat, g_feat);
    cudaGetSymbolAddress((void**)&p_hA, g_hA);
    cudaGetSymbolAddress((void**)&p_hB, g_hB);

    const int SMEM_BYTES = 2 * (BM * BK + BK * BN) * 4;   // 64 KB
    cudaFuncSetAttribute(gemm_tc_kernel,
                         cudaFuncAttributeMaxDynamicSharedMemorySize, SMEM_BYTES);

    dim3 ggrid(256 / BN, (N_NODES + BM - 1) / BM);
    int nw4 = (N_NODES * HEADS + 7) / 8;
    int nw1 = (N_NODES + 7) / 8;

    // CSR build interleaved with layer-0 GEMM (gemm0 placed at launch index 3
    // so the fixed ncu capture slot profiles the heavy kernel).
    zero_kernel<<<(N_NODES + 255) / 256, 256>>>();                  // 0
    hist_kernel<<<(N_EDGES + 255) / 256, 256>>>(dst);               // 1
    scan_offsets_kernel<<<1, 1024>>>();                             // 2
    gemm_tc_kernel<<<ggrid, 256, SMEM_BYTES>>>(feats, W0, p_feat, N_NODES, 512);  // 3 (profiled)
    scatter_kernel<<<(N_EDGES + 255) / 256, 256>>>(src, dst);       // 4
    elr4_kernel<<<nw4, 256>>>(al0, ar0);                            // 5
    agg4_kernel<<<nw4, 256>>>(b0, p_hA);                            // 6

    // layer 1: 256 -> 4x64, relu
    gemm_tc_kernel<<<ggrid, 256, SMEM_BYTES>>>(p_hA, W1, p_feat, N_NODES, 256);
    elr4_kernel<<<nw4, 256>>>(al1, ar1);
    agg4_kernel<<<nw4, 256>>>(b1, p_hB);

    // layer 2: 256 -> 1x256, no activation
    gemm_tc_kernel<<<ggrid, 256, SMEM_BYTES>>>(p_hB, W2, p_feat, N_NODES, 256);
    elr1_kernel<<<nw1, 256>>>(al2, ar2);
    agg1_kernel<<<nw1, 256>>>(b2, out);
}

// round 6
// speedup vs baseline: 1.1794x; 1.1794x over previous
#include <cuda_runtime.h>
#include <cuda_bf16.h>
#include <math.h>

#define N_NODES 50000
#define N_EDGES 800000
#define HID 256
#define HEADS 4
#define DH 64
#define NEG 0.2f

#define W0_ELEMS (512 * 256)
#define W1_ELEMS (256 * 256)
#define W2_ELEMS (256 * 256)
#define W_TOTAL (W0_ELEMS + W1_ELEMS + W2_ELEMS)

// ------------------------- device scratch -------------------------
__device__ float g_feat[N_NODES * HID];            // projected features fp32 (for elr)
__device__ __nv_bfloat16 g_featb[N_NODES * HID];   // projected features bf16 (for gather)
__device__ float g_hA[N_NODES * HID];              // layer-0 output
__device__ float g_hB[N_NODES * HID];              // layer-1 output
__device__ float g_el[N_NODES * HEADS];
__device__ float g_er[N_NODES * HEADS];
__device__ float g_e[(size_t)N_EDGES * HEADS];     // per-edge scores, heads interleaved
__device__ float g_W[W_TOTAL];                     // tf32-pre-rounded weights
__device__ int   g_deg[N_NODES];
__device__ int   g_pos[N_NODES];
__device__ int   g_off[N_NODES + 1];
__device__ int   g_srcs[N_EDGES];

__device__ __forceinline__ unsigned f2tf32(float f) {
    unsigned u;
    asm("cvt.rna.tf32.f32 %0, %1;" : "=r"(u) : "f"(f));
    return u;
}

// ------------------------- weight pre-rounding -------------------------
__global__ void wround_kernel(const float* __restrict__ W0,
                              const float* __restrict__ W1,
                              const float* __restrict__ W2) {
    int i = blockIdx.x * blockDim.x + threadIdx.x;
    if (i < W0_ELEMS) g_W[i] = __uint_as_float(f2tf32(W0[i]));
    else if (i < W0_ELEMS + W1_ELEMS) g_W[i] = __uint_as_float(f2tf32(W1[i - W0_ELEMS]));
    else if (i < W_TOTAL) g_W[i] = __uint_as_float(f2tf32(W2[i - W0_ELEMS - W1_ELEMS]));
}

// ------------------------- CSR build -------------------------
__global__ void zero_kernel() {
    int i = blockIdx.x * blockDim.x + threadIdx.x;
    if (i < N_NODES) { g_deg[i] = 0; g_pos[i] = 0; }
}

__global__ void hist_kernel(const int* __restrict__ dst) {
    int i = blockIdx.x * blockDim.x + threadIdx.x;
    if (i < N_EDGES) atomicAdd(&g_deg[dst[i]], 1);
}

__global__ void scan_offsets_kernel() {
    __shared__ int sums[1024];
    const int SEG = (N_NODES + 1023) / 1024;
    int t = threadIdx.x;
    int b0 = t * SEG;
    int s = 0;
    for (int i = 0; i < SEG; i++) {
        int idx = b0 + i;
        if (idx < N_NODES) s += g_deg[idx];
    }
    sums[t] = s;
    __syncthreads();
    for (int o = 1; o < 1024; o <<= 1) {
        int v = (t >= o) ? sums[t - o] : 0;
        __syncthreads();
        sums[t] += v;
        __syncthreads();
    }
    int run = sums[t] - s;
    for (int i = 0; i < SEG; i++) {
        int idx = b0 + i;
        if (idx < N_NODES) { g_off[idx] = run; run += g_deg[idx]; }
    }
    if (t == 1023) g_off[N_NODES] = sums[1023];
}

__global__ void scatter_kernel(const int* __restrict__ src, const int* __restrict__ dst) {
    int i = blockIdx.x * blockDim.x + threadIdx.x;
    if (i < N_EDGES) {
        int d = dst[i];
        int p = atomicAdd(&g_pos[d], 1);
        g_srcs[g_off[d] + p] = src[i];
    }
}

// ------------------------- TF32 tensor-core GEMM -------------------------
// C[M,256] = A[M,K] @ B[K,256]. Block tile 128x256 (full width), BK=32,
// 512 threads = 16 warps (2 x 8), warp tile 64x32 = 4x4 m16n8k8.
// A: register-staged + tf32 RN cvt + swizzled STS. B: pre-rounded, cp.async.
#define BM 128
#define BN 256
#define BK 32

__device__ __forceinline__ void mma_tf32(float* c, const unsigned* a, const unsigned* b) {
    asm volatile(
        "mma.sync.aligned.m16n8k8.row.col.f32.tf32.tf32.f32 "
        "{%0,%1,%2,%3}, {%4,%5,%6,%7}, {%8,%9}, {%0,%1,%2,%3};\n"
        : "+f"(c[0]), "+f"(c[1]), "+f"(c[2]), "+f"(c[3])
        : "r"(a[0]), "r"(a[1]), "r"(a[2]), "r"(a[3]), "r"(b[0]), "r"(b[1]));
}

__device__ __forceinline__ void cp16(unsigned smem_dst, const void* gptr) {
    asm volatile("cp.async.cg.shared.global [%0], [%1], 16;\n" :: "r"(smem_dst), "l"(gptr));
}

extern __shared__ unsigned g_smem[];   // A: 2*4096, B: 2*8192 words = 96KB

__global__ __launch_bounds__(512) void gemm_tc_kernel(
    const float* __restrict__ A, const float* __restrict__ B,
    float* __restrict__ C, __nv_bfloat16* __restrict__ Cb,
    int M, int K)
{
    unsigned* As = g_smem;                  // 2 * BM*BK
    unsigned* Bs = g_smem + 2 * BM * BK;    // 2 * BK*BN
    unsigned BsAddr = (unsigned)__cvta_generic_to_shared(Bs);

    int tid = threadIdx.x;
    int lane = tid & 31;
    int w = tid >> 5;
    int wm = w >> 3;          // 0..1  (64 rows each)
    int wn = w & 7;           // 0..7  (32 cols each)
    int rowBase = blockIdx.x * BM;

    float c[4][4][4];
#pragma unroll
    for (int t = 0; t < 4; t++)
#pragma unroll
        for (int u = 0; u < 4; u++)
#pragma unroll
            for (int j = 0; j < 4; j++) c[t][u][j] = 0.f;

    // A staging map: 2 passes of 64 rows
    int am_ld = tid >> 3;            // 0..63
    int ak_ld = (tid & 7) << 2;      // 0,4,...,28
    // B cp.async map: 4 passes of 8 rows
    int bk_ld = tid >> 6;            // 0..7
    int bn_ld = (tid & 63) << 2;     // 0..252

    float4 ra[2];

#define LOADA(k0)                                                              \
    {                                                                          \
        _Pragma("unroll")                                                      \
        for (int p = 0; p < 2; p++) {                                          \
            int row = rowBase + p * 64 + am_ld;                                \
            ra[p] = (row < M)                                                  \
                ? *(const float4*)(A + (size_t)row * K + (k0) + ak_ld)         \
                : make_float4(0.f, 0.f, 0.f, 0.f);                             \
        }                                                                      \
    }

#define STOREA(buf)                                                            \
    {                                                                          \
        unsigned* Ab = As + (buf) * (BM * BK);                                 \
        _Pragma("unroll")                                                      \
        for (int p = 0; p < 2; p++) {                                          \
            int m = p * 64 + am_ld;                                            \
            int idx = m * BK + (ak_ld ^ ((m & 7) << 2));                       \
            uint4 v;                                                           \
            v.x = f2tf32(ra[p].x); v.y = f2tf32(ra[p].y);                      \
            v.z = f2tf32(ra[p].z); v.w = f2tf32(ra[p].w);                      \
            *(uint4*)&Ab[idx] = v;                                             \
        }                                                                      \
    }

#define CPB(buf, k0)                                                           \
    {                                                                          \
        unsigned base = BsAddr + (buf) * (BK * BN * 4);                        \
        _Pragma("unroll")                                                      \
        for (int p = 0; p < 4; p++) {                                          \
            int k = p * 8 + bk_ld;                                             \
            int idx = k * BN + (bn_ld ^ ((k & 3) << 3));                       \
            cp16(base + idx * 4, B + (size_t)((k0) + k) * 256 + bn_ld);        \
        }                                                                      \
        asm volatile("cp.async.commit_group;\n");                              \
    }

    int KS = K / BK;
    LOADA(0);
    CPB(0, 0);
    STOREA(0);
    asm volatile("cp.async.wait_group 0;\n");
    __syncthreads();

    for (int it = 0; it < KS; ++it) {
        int cur = it & 1;
        unsigned* Ab = As + cur * (BM * BK);
        unsigned* Bb = Bs + cur * (BK * BN);
        if (it + 1 < KS) {
            LOADA((it + 1) * BK);
            CPB(cur ^ 1, (it + 1) * BK);
        }

#pragma unroll
        for (int kk = 0; kk < 4; kk++) {
            int kb = kk * 8;
            unsigned af[4][4], bf[4][2];
#pragma unroll
            for (int t = 0; t < 4; t++) {
                int r  = wm * 64 + t * 16 + (lane >> 2);
                int r8 = r + 8;
                int c0 = kb + (lane & 3);
                int sw  = (r  & 7) << 2;
                int sw8 = (r8 & 7) << 2;
                af[t][0] = Ab[r  * BK + ( c0      ^ sw )];
                af[t][1] = Ab[r8 * BK + ( c0      ^ sw8)];
                af[t][2] = Ab[r  * BK + ((c0 + 4) ^ sw )];
                af[t][3] = Ab[r8 * BK + ((c0 + 4) ^ sw8)];
            }
#pragma unroll
            for (int u = 0; u < 4; u++) {
                int n  = wn * 32 + u * 8 + (lane >> 2);
                int k0 = kb + (lane & 3);
                int k1 = k0 + 4;
                bf[u][0] = Bb[k0 * BN + (n ^ ((k0 & 3) << 3))];
                bf[u][1] = Bb[k1 * BN + (n ^ ((k1 & 3) << 3))];
            }
#pragma unroll
            for (int t = 0; t < 4; t++)
#pragma unroll
                for (int u = 0; u < 4; u++)
                    mma_tf32(c[t][u], af[t], bf[u]);
        }

        if (it + 1 < KS) STOREA(cur ^ 1);
        asm volatile("cp.async.wait_group 0;\n");
        __syncthreads();
    }

    // epilogue: fp32 + bf16 copies
#pragma unroll
    for (int t = 0; t < 4; t++) {
        int r  = rowBase + wm * 64 + t * 16 + (lane >> 2);
        int r8 = r + 8;
#pragma unroll
        for (int u = 0; u < 4; u++) {
            int col = wn * 32 + u * 8 + ((lane & 3) << 1);
            if (r < M) {
                float2 v = make_float2(c[t][u][0], c[t][u][1]);
                *(float2*)(C + (size_t)r * 256 + col) = v;
                *(__nv_bfloat162*)(Cb + (size_t)r * 256 + col) = __float22bfloat162_rn(v);
            }
            if (r8 < M) {
                float2 v = make_float2(c[t][u][2], c[t][u][3]);
                *(float2*)(C + (size_t)r8 * 256 + col) = v;
                *(__nv_bfloat162*)(Cb + (size_t)r8 * 256 + col) = __float22bfloat162_rn(v);
            }
        }
    }
#undef LOADA
#undef STOREA
#undef CPB
}

// ------------------------- el/er projections (fp32 feat) -------------------------
__global__ __launch_bounds__(256) void elr4_kernel(
    const float* __restrict__ al, const float* __restrict__ ar)
{
    int w = blockIdx.x * 8 + (threadIdx.x >> 5);
    if (w >= N_NODES * HEADS) return;
    int lane = threadIdx.x & 31;
    int n = w >> 2, h = w & 3;
    const float* f = g_feat + (size_t)n * HID + h * DH;
    float f0 = f[lane], f1 = f[lane + 32];
    float a0 = al[h * DH + lane], a1 = al[h * DH + lane + 32];
    float r0 = ar[h * DH + lane], r1 = ar[h * DH + lane + 32];
    float pe = f0 * a0 + f1 * a1;
    float pr = f0 * r0 + f1 * r1;
#pragma unroll
    for (int o = 16; o; o >>= 1) {
        pe += __shfl_xor_sync(0xffffffffu, pe, o);
        pr += __shfl_xor_sync(0xffffffffu, pr, o);
    }
    if (lane == 0) { g_el[w] = pe; g_er[w] = pr; }
}

__global__ __launch_bounds__(256) void elr1_kernel(
    const float* __restrict__ al, const float* __restrict__ ar)
{
    int n = blockIdx.x * 8 + (threadIdx.x >> 5);
    if (n >= N_NODES) return;
    int lane = threadIdx.x & 31;
    const float* f = g_feat + (size_t)n * HID;
    float pe = 0.f, pr = 0.f;
#pragma unroll
    for (int j = 0; j < 8; j++) {
        float fv = f[lane + 32 * j];
        pe += fv * al[lane + 32 * j];
        pr += fv * ar[lane + 32 * j];
    }
#pragma unroll
    for (int o = 16; o; o >>= 1) {
        pe += __shfl_xor_sync(0xffffffffu, pe, o);
        pr += __shfl_xor_sync(0xffffffffu, pr, o);
    }
    if (lane == 0) { g_el[n] = pe; g_er[n] = pr; }
}

// ------------------------- aggregation (merged heads, bf16 gather) -------------
// warp per node; all 4 heads. lane owns 8 features (lane*8..lane*8+7), head = lane>>3.
__global__ __launch_bounds__(256) void agg4_kernel(
    const float* __restrict__ bvec, float* __restrict__ out)
{
    int n = blockIdx.x * 8 + (threadIdx.x >> 5);
    if (n >= N_NODES) return;
    int lane = threadIdx.x & 31;
    int beg = g_off[n], end = g_off[n + 1];
    float4 er4 = *(const float4*)(g_er + 4 * n);

    float4 mx = make_float4(-3.4e38f, -3.4e38f, -3.4e38f, -3.4e38f);
    for (int i = beg + lane; i < end; i += 32) {
        int s = g_srcs[i];
        float4 el4 = *(const float4*)(g_el + 4 * s);
        float4 ev;
        ev.x = el4.x + er4.x; ev.x = (ev.x > 0.f) ? ev.x : ev.x * NEG;
        ev.y = el4.y + er4.y; ev.y = (ev.y > 0.f) ? ev.y : ev.y * NEG;
        ev.z = el4.z + er4.z; ev.z = (ev.z > 0.f) ? ev.z : ev.z * NEG;
        ev.w = el4.w + er4.w; ev.w = (ev.w > 0.f) ? ev.w : ev.w * NEG;
        *(float4*)(g_e + (size_t)4 * i) = ev;
        mx.x = fmaxf(mx.x, ev.x); mx.y = fmaxf(mx.y, ev.y);
        mx.z = fmaxf(mx.z, ev.z); mx.w = fmaxf(mx.w, ev.w);
    }
#pragma unroll
    for (int o = 16; o; o >>= 1) {
        mx.x = fmaxf(mx.x, __shfl_xor_sync(0xffffffffu, mx.x, o));
        mx.y = fmaxf(mx.y, __shfl_xor_sync(0xffffffffu, mx.y, o));
        mx.z = fmaxf(mx.z, __shfl_xor_sync(0xffffffffu, mx.z, o));
        mx.w = fmaxf(mx.w, __shfl_xor_sync(0xffffffffu, mx.w, o));
    }

    float4 se = make_float4(0.f, 0.f, 0.f, 0.f);
    for (int i = beg + lane; i < end; i += 32) {
        float4 ev = *(const float4*)(g_e + (size_t)4 * i);
        ev.x = __expf(ev.x - mx.x); ev.y = __expf(ev.y - mx.y);
        ev.z = __expf(ev.z - mx.z); ev.w = __expf(ev.w - mx.w);
        *(float4*)(g_e + (size_t)4 * i) = ev;
        se.x += ev.x; se.y += ev.y; se.z += ev.z; se.w += ev.w;
    }
#pragma unroll
    for (int o = 16; o; o >>= 1) {
        se.x += __shfl_xor_sync(0xffffffffu, se.x, o);
        se.y += __shfl_xor_sync(0xffffffffu, se.y, o);
        se.z += __shfl_xor_sync(0xffffffffu, se.z, o);
        se.w += __shfl_xor_sync(0xffffffffu, se.w, o);
    }
    int h = lane >> 3;
    float seh = (h == 0) ? se.x : (h == 1) ? se.y : (h == 2) ? se.z : se.w;
    float invh = 1.f / seh;
    __syncwarp();

    float acc[8];
#pragma unroll
    for (int j = 0; j < 8; j++) acc[j] = 0.f;
    for (int i = beg; i < end; i++) {
        int s = g_srcs[i];
        float a = g_e[(size_t)4 * i + h] * invh;
        uint4 v = *(const uint4*)(g_featb + (size_t)s * HID + lane * 8);
        float2 f0 = __bfloat1622float2(*(__nv_bfloat162*)&v.x);
        float2 f1 = __bfloat1622float2(*(__nv_bfloat162*)&v.y);
        float2 f2 = __bfloat1622float2(*(__nv_bfloat162*)&v.z);
        float2 f3 = __bfloat1622float2(*(__nv_bfloat162*)&v.w);
        acc[0] = fmaf(a, f0.x, acc[0]); acc[1] = fmaf(a, f0.y, acc[1]);
        acc[2] = fmaf(a, f1.x, acc[2]); acc[3] = fmaf(a, f1.y, acc[3]);
        acc[4] = fmaf(a, f2.x, acc[4]); acc[5] = fmaf(a, f2.y, acc[5]);
        acc[6] = fmaf(a, f3.x, acc[6]); acc[7] = fmaf(a, f3.y, acc[7]);
    }
#pragma unroll
    for (int j = 0; j < 8; j++) {
        float o = acc[j] + bvec[lane * 8 + j];
        out[(size_t)n * HID + lane * 8 + j] = fmaxf(o, 0.f);
    }
}

// layer 2: single head, D=256, no activation
__global__ __launch_bounds__(256) void agg1_kernel(
    const float* __restrict__ bvec, float* __restrict__ out)
{
    int n = blockIdx.x * 8 + (threadIdx.x >> 5);
    if (n >= N_NODES) return;
    int lane = threadIdx.x & 31;
    int beg = g_off[n], end = g_off[n + 1];
    float ern = g_er[n];

    float mx = -3.4e38f;
    for (int i = beg + lane; i < end; i += 32) {
        float ev = g_el[g_srcs[i]] + ern;
        ev = (ev > 0.f) ? ev : ev * NEG;
        g_e[i] = ev;
        mx = fmaxf(mx, ev);
    }
#pragma unroll
    for (int o = 16; o; o >>= 1) mx = fmaxf(mx, __shfl_xor_sync(0xffffffffu, mx, o));

    float se = 0.f;
    for (int i = beg + lane; i < end; i += 32) {
        float ex = __expf(g_e[i] - mx);
        g_e[i] = ex;
        se += ex;
    }
#pragma unroll
    for (int o = 16; o; o >>= 1) se += __shfl_xor_sync(0xffffffffu, se, o);
    float inv = 1.f / se;
    __syncwarp();

    float acc[8];
#pragma unroll
    for (int j = 0; j < 8; j++) acc[j] = 0.f;
    for (int i = beg; i < end; i++) {
        int s = g_srcs[i];
        float a = g_e[i] * inv;
        uint4 v = *(const uint4*)(g_featb + (size_t)s * HID + lane * 8);
        float2 f0 = __bfloat1622float2(*(__nv_bfloat162*)&v.x);
        float2 f1 = __bfloat1622float2(*(__nv_bfloat162*)&v.y);
        float2 f2 = __bfloat1622float2(*(__nv_bfloat162*)&v.z);
        float2 f3 = __bfloat1622float2(*(__nv_bfloat162*)&v.w);
        acc[0] = fmaf(a, f0.x, acc[0]); acc[1] = fmaf(a, f0.y, acc[1]);
        acc[2] = fmaf(a, f1.x, acc[2]); acc[3] = fmaf(a, f1.y, acc[3]);
        acc[4] = fmaf(a, f2.x, acc[4]); acc[5] = fmaf(a, f2.y, acc[5]);
        acc[6] = fmaf(a, f3.x, acc[6]); acc[7] = fmaf(a, f3.y, acc[7]);
    }
#pragma unroll
    for (int j = 0; j < 8; j++)
        out[(size_t)n * HID + lane * 8 + j] = acc[j] + bvec[lane * 8 + j];
}

// ------------------------- host launch -------------------------
extern "C" void kernel_launch(void* const* d_in, const int* in_sizes, int n_in,
                              void* d_out, int out_size)
{
    const float* feats = (const float*)d_in[0];
    const int*   src   = (const int*)d_in[1];
    const int*   dst   = (const int*)d_in[2];
    const float* W0  = (const float*)d_in[3];
    const float* al0 = (const float*)d_in[4];
    const float* ar0 = (const float*)d_in[5];
    const float* b0  = (const float*)d_in[6];
    const float* W1  = (const float*)d_in[7];
    const float* al1 = (const float*)d_in[8];
    const float* ar1 = (const float*)d_in[9];
    const float* b1  = (const float*)d_in[10];
    const float* W2  = (const float*)d_in[11];
    const float* al2 = (const float*)d_in[12];
    const float* ar2 = (const float*)d_in[13];
    const float* b2  = (const float*)d_in[14];
    float* out = (float*)d_out;

    float *p_feat, *p_hA, *p_hB, *p_W;
    __nv_bfloat16* p_featb;
    cudaGetSymbolAddress((void**)&p_feat, g_feat);
    cudaGetSymbolAddress((void**)&p_featb, g_featb);
    cudaGetSymbolAddress((void**)&p_hA, g_hA);
    cudaGetSymbolAddress((void**)&p_hB, g_hB);
    cudaGetSymbolAddress((void**)&p_W, g_W);

    const int SMEM_BYTES = 2 * (BM * BK + BK * BN) * 4;   // 96 KB
    cudaFuncSetAttribute(gemm_tc_kernel,
                         cudaFuncAttributeMaxDynamicSharedMemorySize, SMEM_BYTES);

    int ggrid = (N_NODES + BM - 1) / BM;   // 391, full-width tiles
    int nw4 = (N_NODES * HEADS + 7) / 8;
    int nwN = (N_NODES + 7) / 8;

    // gemm0 placed at launch index 3 (fixed ncu capture slot).
    wround_kernel<<<(W_TOTAL + 255) / 256, 256>>>(W0, W1, W2);        // 0
    zero_kernel<<<(N_NODES + 255) / 256, 256>>>();                    // 1
    hist_kernel<<<(N_EDGES + 255) / 256, 256>>>(dst);                 // 2
    gemm_tc_kernel<<<ggrid, 512, SMEM_BYTES>>>(feats, p_W, p_feat, p_featb, N_NODES, 512);  // 3
    scan_offsets_kernel<<<1, 1024>>>();                               // 4
    scatter_kernel<<<(N_EDGES + 255) / 256, 256>>>(src, dst);         // 5
    elr4_kernel<<<nw4, 256>>>(al0, ar0);                              // 6
    agg4_kernel<<<nwN, 256>>>(b0, p_hA);                              // 7

    // layer 1
    gemm_tc_kernel<<<ggrid, 512, SMEM_BYTES>>>(p_hA, p_W + W0_ELEMS, p_feat, p_featb, N_NODES, 256);
    elr4_kernel<<<nw4, 256>>>(al1, ar1);
    agg4_kernel<<<nwN, 256>>>(b1, p_hB);

    // layer 2
    gemm_tc_kernel<<<ggrid, 512, SMEM_BYTES>>>(p_hB, p_W + W0_ELEMS + W1_ELEMS, p_feat, p_featb, N_NODES, 256);
    elr1_kernel<<<nwN, 256>>>(al2, ar2);
    agg1_kernel<<<nwN, 256>>>(b2, out);
}